// round 3
// baseline (speedup 1.0000x reference)
#include <cuda_runtime.h>

// x[32, 336, 32, 32] fp32, moving-avg k=25 (replicate pad), seasonal period 24
#define BB     32
#define CC     336
#define KS     25
#define PE     24
#define NG     (CC / PE)          // 14
#define HWW    1024               // 32*32 floats
#define HW2    (HWW / 2)          // 512 float2 per (b, c) plane
#define NELEM  ((size_t)BB * CC * HWW)

#define COLS2   16                // float2-columns per block
#define NTHREAD (COLS2 * NG)      // 224
#define NBLK    ((BB * HW2) / COLS2)  // 16384/16 = 1024

__global__ __launch_bounds__(NTHREAD, 6)
void decomp_kernel(const float2* __restrict__ x2,
                   float2* __restrict__ To,
                   float2* __restrict__ So,
                   float2* __restrict__ Ro)
{
    __shared__ float2 acc[PE][COLS2];   // phase sums per column

    const int tx = threadIdx.x;         // [0,16) float2 column in block
    const int g  = threadIdx.y;         // [0,14) channel group
    const int col2 = blockIdx.x * COLS2 + tx;   // [0, 16384)
    const int b   = col2 >> 9;          // col2 / 512
    const int hw2 = col2 & (HW2 - 1);

    const size_t base = (size_t)b * CC * HW2 + hw2;
    const float2* __restrict__ xp = x2 + base;

    const float inv_k = 1.0f / (float)KS;
    const float inv_g = 1.0f / (float)NG;
    const int   c0    = g * PE;

    // zero the reduction buffer
    {
        int lin = threadIdx.y * COLS2 + threadIdx.x;
        float* s = &acc[0][0].x;
        for (int i = lin; i < PE * COLS2 * 2; i += NTHREAD) s[i] = 0.0f;
    }

    // initial window sum at c = c0
    float wx0 = 0.0f, wy0 = 0.0f;
    #pragma unroll
    for (int j = -12; j <= 12; j++) {
        int cc = c0 + j;
        cc = cc < 0 ? 0 : (cc > CC - 1 ? CC - 1 : cc);
        float2 v = xp[(size_t)cc * HW2];
        wx0 += v.x; wy0 += v.y;
    }

    // ---- Pass A: trend (write To) + per-phase sums of detrended ----
    float wx = wx0, wy = wy0;
    #pragma unroll
    for (int p = 0; p < PE; p++) {
        const int c = c0 + p;
        float Tx = wx * inv_k, Ty = wy * inv_k;
        float2 xc = xp[(size_t)c * HW2];
        float2 t; t.x = Tx; t.y = Ty;
        To[base + (size_t)c * HW2] = t;
        atomicAdd(&acc[p][tx].x, xc.x - Tx);
        atomicAdd(&acc[p][tx].y, xc.y - Ty);
        int cin  = c + 13; if (cin  > CC - 1) cin  = CC - 1;
        int cout = c - 12; if (cout < 0)      cout = 0;
        float2 a = xp[(size_t)cin * HW2];
        float2 d = xp[(size_t)cout * HW2];
        wx += a.x - d.x;
        wy += a.y - d.y;
    }

    __syncthreads();

    // ---- Pass B: recompute identical trend, emit S and R ----
    wx = wx0; wy = wy0;
    #pragma unroll
    for (int p = 0; p < PE; p++) {
        const int c = c0 + p;
        float Tx = wx * inv_k, Ty = wy * inv_k;
        float2 xc = xp[(size_t)c * HW2];   // L1/L2 hit
        float2 sacc = acc[p][tx];
        float2 S; S.x = sacc.x * inv_g; S.y = sacc.y * inv_g;
        float2 R; R.x = (xc.x - Tx) - S.x; R.y = (xc.y - Ty) - S.y;
        So[base + (size_t)c * HW2] = S;
        Ro[base + (size_t)c * HW2] = R;
        int cin  = c + 13; if (cin  > CC - 1) cin  = CC - 1;
        int cout = c - 12; if (cout < 0)      cout = 0;
        float2 a = xp[(size_t)cin * HW2];
        float2 d = xp[(size_t)cout * HW2];
        wx += a.x - d.x;
        wy += a.y - d.y;
    }
}

extern "C" void kernel_launch(void* const* d_in, const int* in_sizes, int n_in,
                              void* d_out, int out_size)
{
    const float2* x = (const float2*)d_in[0];
    float* out = (float*)d_out;
    float2* To = (float2*)out;
    float2* So = (float2*)(out + NELEM);
    float2* Ro = (float2*)(out + 2 * NELEM);
    dim3 blk(COLS2, NG);
    decomp_kernel<<<NBLK, blk>>>(x, To, So, Ro);
}

// round 4
// speedup vs baseline: 2.2781x; 2.2781x over previous
#include <cuda_runtime.h>

// x[32, 336, 32, 32] fp32, moving-avg k=25 (replicate pad), seasonal period 24
#define BB     32
#define CC     336
#define KS     25
#define PE     24
#define NG     (CC / PE)          // 14
#define HWW    1024
#define NCOL   (BB * HWW)         // 32768 columns
#define NELEM  ((size_t)BB * CC * HWW)

#define COLS    32                // fp32 columns per block (one warp-width)
#define NTHREAD (COLS * NG)       // 448

__global__ __launch_bounds__(NTHREAD, 3)
void decomp_kernel(const float* __restrict__ x,
                   float* __restrict__ To,
                   float* __restrict__ So,
                   float* __restrict__ Ro)
{
    __shared__ float xd_s[NG][PE][COLS];  // detrended values (42 KB)
    __shared__ float acc[PE][COLS];       // seasonal means   (3 KB)

    const int tx = threadIdx.x;           // [0,32) column lane
    const int g  = threadIdx.y;           // [0,14) channel group (one warp each)
    const int col = blockIdx.x * COLS + tx;
    const int b  = col >> 10;
    const int hw = col & (HWW - 1);

    const size_t base = (size_t)b * CC * HWW + hw;
    const float* __restrict__ xp = x + base;

    const float inv_k = 1.0f / (float)KS;
    const float inv_g = 1.0f / (float)NG;
    const int   c0    = g * PE;

    // initial window sum at c = c0: sum_{j=-12..12} x[clamp(c0+j)]
    float wsum = 0.0f;
    #pragma unroll
    for (int j = -12; j <= 12; j++) {
        int cc = c0 + j;
        cc = cc < 0 ? 0 : (cc > CC - 1 ? CC - 1 : cc);
        wsum += xp[(size_t)cc * HWW];
    }

    // ---- Pass A: trend (write To), stash detrended in smem ----
    #pragma unroll
    for (int p = 0; p < PE; p++) {
        const int c = c0 + p;
        float T  = wsum * inv_k;
        float xc = xp[(size_t)c * HWW];
        To[base + (size_t)c * HWW] = T;
        xd_s[g][p][tx] = xc - T;
        int cin  = c + 13; if (cin  > CC - 1) cin  = CC - 1;
        int cout = c - 12; if (cout < 0)      cout = 0;
        wsum += xp[(size_t)cin * HWW] - xp[(size_t)cout * HWW];
    }

    __syncthreads();

    // ---- Cross-group reduction (no atomics): each thread owns (p, t) pairs ----
    {
        const int lin = threadIdx.y * COLS + threadIdx.x;
        for (int idx = lin; idx < PE * COLS; idx += NTHREAD) {
            const int p = idx >> 5;
            const int t = idx & 31;
            float s = 0.0f;
            #pragma unroll
            for (int gg = 0; gg < NG; gg++) s += xd_s[gg][p][t];
            acc[p][t] = s * inv_g;
        }
    }

    __syncthreads();

    // ---- Pass B: emit seasonal + residual from smem (no global re-reads) ----
    #pragma unroll
    for (int p = 0; p < PE; p++) {
        const int c = c0 + p;
        float S  = acc[p][tx];
        float xd = xd_s[g][p][tx];
        So[base + (size_t)c * HWW] = S;
        Ro[base + (size_t)c * HWW] = xd - S;
    }
}

extern "C" void kernel_launch(void* const* d_in, const int* in_sizes, int n_in,
                              void* d_out, int out_size)
{
    const float* x = (const float*)d_in[0];
    float* out = (float*)d_out;
    float* To = out;
    float* So = out + NELEM;
    float* Ro = out + 2 * NELEM;
    dim3 blk(COLS, NG);
    decomp_kernel<<<NCOL / COLS, blk>>>(x, To, So, Ro);
}